// round 1
// baseline (speedup 1.0000x reference)
#include <cuda_runtime.h>
#include <math.h>

// Problem constants
#define B_SZ   128
#define T_ENC  64
#define D_IN   2048
#define T_DEC  32
#define D_W    300
#define H_SZ   512
#define G4     2048   // 4*H

// ---------------- scratch (device globals; no allocation) ----------------
__device__ float g_Xg_enc[(size_t)T_ENC * B_SZ * G4];   // 64 MB: x-part of encoder gates (+bias)
__device__ float g_Xg_dec[(size_t)T_DEC * B_SZ * G4];   // 32 MB
__device__ float g_Adec [(size_t)T_DEC * B_SZ * D_W];   // gathered caption embeddings, row m=t*128+b
__device__ float g_P    [4 * B_SZ * G4];                // split-K partials of h@Wh
__device__ float g_h    [B_SZ * H_SZ];
__device__ float g_c    [B_SZ * H_SZ];
__device__ float g_dech [(size_t)T_DEC * B_SZ * H_SZ];  // decoder hidden states, row m=t*128+b

__device__ __forceinline__ float sigmoidf_(float x) { return 1.0f / (1.0f + expf(-x)); }

// ---------------- generic 128x128x8 SGEMM, double-buffered ----------------
// C[M,N] = A[M,K] @ B[K,N] + bias[N]
// AMODE 0: A row m at A + m*lda
// AMODE 1: frames permute: m = t*128+b -> A + ((b*64 + t))*lda   (lda = 2048)
// CMODE 0: C[m*ldc + n]
// CMODE 1: decoder output permute: m = t*128+b -> C[(b*32 + t)*300 + n]
template <int AMODE, int CMODE>
__global__ __launch_bounds__(256, 2)
void sgemm128(int M, int N, int K,
              const float* __restrict__ A, int lda,
              const float* __restrict__ Bm, int ldb,
              const float* __restrict__ bias,
              float* __restrict__ C, int ldc)
{
    __shared__ float As[2][8][132];
    __shared__ float Bs[2][8][128];

    const int tid = threadIdx.x;
    const int bm = blockIdx.y * 128;
    const int bn = blockIdx.x * 128;

    const int arow = tid >> 1;          // 0..127
    const int acol = (tid & 1) * 4;     // 0 or 4
    const int brow = tid >> 5;          // 0..7
    const int bcol = (tid & 31) * 4;    // 0..124
    const int ty8 = (tid >> 4) * 8;     // row group
    const int tx8 = (tid & 15) * 8;     // col group

    size_t aoff;
    {
        int m = bm + arow;  // M is always a multiple of 128 here
        if (AMODE == 1) aoff = (size_t)((m & 127) * T_ENC + (m >> 7)) * (size_t)lda;
        else            aoff = (size_t)m * (size_t)lda;
    }

    float acc[8][8];
#pragma unroll
    for (int i = 0; i < 8; i++)
#pragma unroll
        for (int j = 0; j < 8; j++) acc[i][j] = 0.0f;

    float pa[4], pb[4];
    const int ntiles = (K + 7) >> 3;

    // prologue fetch tile 0
    {
        int ka = acol;
        if (ka + 3 < K) {
            float4 v = *(const float4*)(A + aoff + ka);
            pa[0] = v.x; pa[1] = v.y; pa[2] = v.z; pa[3] = v.w;
        } else {
#pragma unroll
            for (int i = 0; i < 4; i++) pa[i] = (ka + i < K) ? A[aoff + ka + i] : 0.0f;
        }
        int kb = brow;
        int n = bn + bcol;
        if (kb < K && n + 3 < N) {
            float4 v = *(const float4*)(Bm + (size_t)kb * ldb + n);
            pb[0] = v.x; pb[1] = v.y; pb[2] = v.z; pb[3] = v.w;
        } else {
#pragma unroll
            for (int i = 0; i < 4; i++) pb[i] = (kb < K && n + i < N) ? Bm[(size_t)kb * ldb + n + i] : 0.0f;
        }
#pragma unroll
        for (int i = 0; i < 4; i++) As[0][acol + i][arow] = pa[i];
        *(float4*)&Bs[0][brow][bcol] = make_float4(pb[0], pb[1], pb[2], pb[3]);
    }
    __syncthreads();

    for (int t = 0; t < ntiles; ++t) {
        const int cur = t & 1;
        if (t + 1 < ntiles) {
            int ka = (t + 1) * 8 + acol;
            if (ka + 3 < K) {
                float4 v = *(const float4*)(A + aoff + ka);
                pa[0] = v.x; pa[1] = v.y; pa[2] = v.z; pa[3] = v.w;
            } else {
#pragma unroll
                for (int i = 0; i < 4; i++) pa[i] = (ka + i < K) ? A[aoff + ka + i] : 0.0f;
            }
            int kb = (t + 1) * 8 + brow;
            int n = bn + bcol;
            if (kb < K && n + 3 < N) {
                float4 v = *(const float4*)(Bm + (size_t)kb * ldb + n);
                pb[0] = v.x; pb[1] = v.y; pb[2] = v.z; pb[3] = v.w;
            } else {
#pragma unroll
                for (int i = 0; i < 4; i++) pb[i] = (kb < K && n + i < N) ? Bm[(size_t)kb * ldb + n + i] : 0.0f;
            }
        }
#pragma unroll
        for (int k = 0; k < 8; k++) {
            float a[8], b[8];
            *(float4*)(a)     = *(const float4*)&As[cur][k][ty8];
            *(float4*)(a + 4) = *(const float4*)&As[cur][k][ty8 + 4];
            *(float4*)(b)     = *(const float4*)&Bs[cur][k][tx8];
            *(float4*)(b + 4) = *(const float4*)&Bs[cur][k][tx8 + 4];
#pragma unroll
            for (int i = 0; i < 8; i++)
#pragma unroll
                for (int j = 0; j < 8; j++)
                    acc[i][j] = fmaf(a[i], b[j], acc[i][j]);
        }
        if (t + 1 < ntiles) {
            const int nxt = cur ^ 1;
#pragma unroll
            for (int i = 0; i < 4; i++) As[nxt][acol + i][arow] = pa[i];
            *(float4*)&Bs[nxt][brow][bcol] = make_float4(pb[0], pb[1], pb[2], pb[3]);
        }
        __syncthreads();
    }

    float bj[8];
#pragma unroll
    for (int j = 0; j < 8; j++) {
        int n = bn + tx8 + j;
        bj[j] = (bias != nullptr && n < N) ? bias[n] : 0.0f;
    }
#pragma unroll
    for (int i = 0; i < 8; i++) {
        int m = bm + ty8 + i;
#pragma unroll
        for (int j = 0; j < 8; j++) {
            int n = bn + tx8 + j;
            if (n < N) {
                float v = acc[i][j] + bj[j];
                if (CMODE == 0) {
                    C[(size_t)m * ldc + n] = v;
                } else {
                    int tt = m >> 7;         // timestep
                    int b = m & 127;         // batch
                    C[(size_t)(b * T_DEC + tt) * D_W + n] = v;
                }
            }
        }
    }
}

// ---------------- recurrent GEMM partial: P[ks] = h @ Wh(chunk ks) ----------------
// Tile: 64 rows x (32 hidden units x 4 gates), K-chunk = 128. Grid (16, 2, 4).
__global__ __launch_bounds__(256)
void lstm_partial(const float* __restrict__ Wh)   // Wh: [512][2048] row-major
{
    const int u0 = blockIdx.x * 32;
    const int r0 = blockIdx.y * 64;
    const int ks = blockIdx.z;
    const int k0 = ks * 128;

    __shared__ float Hs[32][68];    // [kk][row]
    __shared__ float Ws[32][128];   // [kk][g*32+hx]

    const int tid = threadIdx.x;
    const int hx = tid & 31;        // hidden unit within tile
    const int rg = tid >> 5;        // row group 0..7 (8 rows each)
    const int lr = tid >> 2;        // 0..63  (H loader row)
    const int lk = (tid & 3) * 8;   // 0,8,16,24 (H loader k offset)

    float acc[8][4];
#pragma unroll
    for (int i = 0; i < 8; i++)
#pragma unroll
        for (int g = 0; g < 4; g++) acc[i][g] = 0.0f;

    for (int kc = 0; kc < 4; ++kc) {
        const int kb = k0 + kc * 32;
        // load H chunk [64 rows x 32 k] transposed
        {
            const float* hp = g_h + (size_t)(r0 + lr) * H_SZ + kb + lk;
            float4 v0 = *(const float4*)hp;
            float4 v1 = *(const float4*)(hp + 4);
            Hs[lk + 0][lr] = v0.x; Hs[lk + 1][lr] = v0.y;
            Hs[lk + 2][lr] = v0.z; Hs[lk + 3][lr] = v0.w;
            Hs[lk + 4][lr] = v1.x; Hs[lk + 5][lr] = v1.y;
            Hs[lk + 6][lr] = v1.z; Hs[lk + 7][lr] = v1.w;
        }
        // load W chunk [32 k x 128 cols]; col c = g*32+hh maps to Wh col g*512+u0+hh
#pragma unroll
        for (int it = 0; it < 4; ++it) {
            int f = it * 1024 + tid * 4;
            int kk = f >> 7;
            int c = f & 127;
            int g = c >> 5;
            int hh = c & 31;
            float4 w = *(const float4*)(Wh + (size_t)(kb + kk) * G4 + g * H_SZ + u0 + hh);
            *(float4*)&Ws[kk][c] = w;
        }
        __syncthreads();
#pragma unroll
        for (int kk = 0; kk < 32; ++kk) {
            float a[8];
            *(float4*)(a)     = *(const float4*)&Hs[kk][rg * 8];
            *(float4*)(a + 4) = *(const float4*)&Hs[kk][rg * 8 + 4];
            float w0 = Ws[kk][hx];
            float w1 = Ws[kk][32 + hx];
            float w2 = Ws[kk][64 + hx];
            float w3 = Ws[kk][96 + hx];
#pragma unroll
            for (int i = 0; i < 8; i++) {
                acc[i][0] = fmaf(a[i], w0, acc[i][0]);
                acc[i][1] = fmaf(a[i], w1, acc[i][1]);
                acc[i][2] = fmaf(a[i], w2, acc[i][2]);
                acc[i][3] = fmaf(a[i], w3, acc[i][3]);
            }
        }
        __syncthreads();
    }

    float* pp = g_P + (size_t)ks * (B_SZ * G4);
#pragma unroll
    for (int i = 0; i < 8; i++) {
        int row = r0 + rg * 8 + i;
#pragma unroll
        for (int g = 0; g < 4; g++)
            pp[(size_t)row * G4 + g * H_SZ + u0 + hx] = acc[i][g];
    }
}

// ---------------- fused gate reduce + LSTM pointwise ----------------
// first==1: encoder step 0 (h=0, c=0): gates = Xg only, c_prev = 0.
__global__ __launch_bounds__(256)
void lstm_pointwise(const float* __restrict__ Xg, int first, float* __restrict__ dech)
{
    int idx = blockIdx.x * blockDim.x + threadIdx.x;
    if (idx >= B_SZ * H_SZ) return;
    int b = idx >> 9;
    int u = idx & (H_SZ - 1);

    const float* xg = Xg + (size_t)b * G4;
    float gi = xg[u];
    float gj = xg[H_SZ + u];
    float gf = xg[2 * H_SZ + u];
    float go = xg[3 * H_SZ + u];

    float cprev = 0.0f;
    if (!first) {
#pragma unroll
        for (int ks = 0; ks < 4; ks++) {
            const float* p = g_P + (size_t)ks * (B_SZ * G4) + (size_t)b * G4;
            gi += p[u];
            gj += p[H_SZ + u];
            gf += p[2 * H_SZ + u];
            go += p[3 * H_SZ + u];
        }
        cprev = g_c[idx];
    }

    float cn = cprev * sigmoidf_(gf + 1.0f) + sigmoidf_(gi) * tanhf(gj);
    float hn = tanhf(cn) * sigmoidf_(go);
    g_c[idx] = cn;
    g_h[idx] = hn;
    if (dech != nullptr) dech[idx] = hn;
}

// ---------------- caption embedding gather ----------------
// Adec[m = t*128+b] = emb_table[ids[b*32+t]]
__global__ void gather_emb(const int* __restrict__ ids, const float* __restrict__ emb,
                           float* __restrict__ Adec)
{
    int m = blockIdx.x;                  // 0..4095
    int t = m >> 7;
    int b = m & 127;
    int id = ids[b * T_DEC + t];
    const float4* src = (const float4*)(emb + (size_t)id * D_W);
    float4* dst = (float4*)(Adec + (size_t)m * D_W);
    for (int k = threadIdx.x; k < D_W / 4; k += blockDim.x) dst[k] = src[k];
}

// ---------------- host launcher ----------------
extern "C" void kernel_launch(void* const* d_in, const int* in_sizes, int n_in,
                              void* d_out, int out_size)
{
    (void)in_sizes; (void)n_in; (void)out_size;
    const float* frames = (const float*)d_in[0];
    const int*   ids    = (const int*)d_in[1];
    const float* emb    = (const float*)d_in[2];
    const float* W_enc  = (const float*)d_in[3];
    const float* b_enc  = (const float*)d_in[4];
    const float* W_dec  = (const float*)d_in[5];
    const float* b_dec  = (const float*)d_in[6];
    const float* W_out  = (const float*)d_in[7];
    const float* b_out  = (const float*)d_in[8];
    float* out = (float*)d_out;

    float *Xge = nullptr, *Xgd = nullptr, *Adec = nullptr, *dech = nullptr;
    cudaGetSymbolAddress((void**)&Xge,  g_Xg_enc);
    cudaGetSymbolAddress((void**)&Xgd,  g_Xg_dec);
    cudaGetSymbolAddress((void**)&Adec, g_Adec);
    cudaGetSymbolAddress((void**)&dech, g_dech);

    // 1. Encoder input gates for all timesteps: [8192,2048] = frames @ W_enc[:2048] + b_enc
    sgemm128<1, 0><<<dim3(G4 / 128, (T_ENC * B_SZ) / 128), 256>>>(
        T_ENC * B_SZ, G4, D_IN, frames, D_IN, W_enc, G4, b_enc, Xge, G4);

    // 2. Encoder recurrence
    const float* Wh_enc = W_enc + (size_t)D_IN * G4;
    for (int t = 0; t < T_ENC; ++t) {
        if (t > 0)
            lstm_partial<<<dim3(16, 2, 4), 256>>>(Wh_enc);
        lstm_pointwise<<<(B_SZ * H_SZ) / 256, 256>>>(
            Xge + (size_t)t * B_SZ * G4, (t == 0) ? 1 : 0, nullptr);
    }

    // 3. Caption embeddings + decoder input gates
    gather_emb<<<T_DEC * B_SZ, 128>>>(ids, emb, Adec);
    sgemm128<0, 0><<<dim3(G4 / 128, (T_DEC * B_SZ) / 128), 256>>>(
        T_DEC * B_SZ, G4, D_W, Adec, D_W, W_dec, G4, b_dec, Xgd, G4);

    // 4. Decoder recurrence (starts from encoder state; h nonzero -> always full step)
    const float* Wh_dec = W_dec + (size_t)D_W * G4;
    for (int t = 0; t < T_DEC; ++t) {
        lstm_partial<<<dim3(16, 2, 4), 256>>>(Wh_dec);
        lstm_pointwise<<<(B_SZ * H_SZ) / 256, 256>>>(
            Xgd + (size_t)t * B_SZ * G4, 0, dech + (size_t)t * B_SZ * H_SZ);
    }

    // 5. Output projection: [4096,512] @ [512,300] + b_out, stored as [B, T_dec, D_w]
    sgemm128<0, 1><<<dim3((D_W + 127) / 128, (T_DEC * B_SZ) / 128), 256>>>(
        T_DEC * B_SZ, D_W, H_SZ, dech, H_SZ, W_out, D_W, b_out, out, D_W);
}

// round 4
// speedup vs baseline: 1.2836x; 1.2836x over previous
#include <cuda_runtime.h>
#include <cuda_bf16.h>
#include <math.h>
#include <stdint.h>

// Problem constants
#define B_SZ   128
#define T_ENC  64
#define D_IN   2048
#define T_DEC  32
#define D_W    300
#define D_WP   320     // padded to multiple of 32
#define H_SZ   512
#define G4     2048    // 4*H
#define M_ENC  (T_ENC * B_SZ)   // 8192
#define M_DEC  (T_DEC * B_SZ)   // 4096

// ---------------- scratch (device globals; no allocation) ----------------
__device__ float g_Xg_enc[(size_t)M_ENC * G4];     // x-part of encoder gates (+bias)
__device__ float g_Xg_dec[(size_t)M_DEC * G4];
__device__ float g_P    [4 * B_SZ * G4];           // split-K partials of h@Wh
__device__ float g_hbuf [2][B_SZ * H_SZ];          // ping-pong h
__device__ float g_c    [B_SZ * H_SZ];
__device__ int   g_cnt  [(T_ENC - 1 + T_DEC) * 32];   // zero-init; last CTA resets its slot

// bf16 hi/lo limb arrays for tensor-core GEMMs (16B aligned for cp.async 16B)
__device__ __align__(16) __nv_bfloat16 g_Afr_h[(size_t)M_ENC * D_IN];
__device__ __align__(16) __nv_bfloat16 g_Afr_l[(size_t)M_ENC * D_IN];
__device__ __align__(16) __nv_bfloat16 g_Bte_h[(size_t)G4 * D_IN];   // W_enc_x^T [2048,2048]
__device__ __align__(16) __nv_bfloat16 g_Bte_l[(size_t)G4 * D_IN];
__device__ __align__(16) __nv_bfloat16 g_Ad_h [(size_t)M_DEC * D_WP];
__device__ __align__(16) __nv_bfloat16 g_Ad_l [(size_t)M_DEC * D_WP];
__device__ __align__(16) __nv_bfloat16 g_Btd_h[(size_t)G4 * D_WP];   // W_dec_x^T [2048,320]
__device__ __align__(16) __nv_bfloat16 g_Btd_l[(size_t)G4 * D_WP];
__device__ __align__(16) __nv_bfloat16 g_Dh_h [(size_t)M_DEC * H_SZ]; // decoder h limbs
__device__ __align__(16) __nv_bfloat16 g_Dh_l [(size_t)M_DEC * H_SZ];
__device__ __align__(16) __nv_bfloat16 g_Bto_h[(size_t)512 * H_SZ];  // W_out^T padded [512,512]
__device__ __align__(16) __nv_bfloat16 g_Bto_l[(size_t)512 * H_SZ];

__device__ __forceinline__ float sigmoidf_(float x) { return 1.0f / (1.0f + expf(-x)); }

// ============================ PTX helpers (baseline ISA only) ============================
__device__ __forceinline__ uint32_t smem_u32_(const void* p) {
    uint32_t a;
    asm("{ .reg .u64 t; cvta.to.shared.u64 t, %1; cvt.u32.u64 %0, t; }" : "=r"(a) : "l"(p));
    return a;
}
__device__ __forceinline__ void cp16_(uint32_t dst, const void* src) {
    asm volatile("cp.async.cg.shared.global [%0], [%1], 16;" :: "r"(dst), "l"(src));
}
__device__ __forceinline__ void cp_commit_() { asm volatile("cp.async.commit_group;" ::: "memory"); }
__device__ __forceinline__ void cp_wait0_()  { asm volatile("cp.async.wait_group 0;" ::: "memory"); }

__device__ __forceinline__ void ldm4_(uint32_t* r, uint32_t addr) {
    asm volatile("ldmatrix.sync.aligned.m8n8.x4.shared.b16 {%0,%1,%2,%3}, [%4];"
                 : "=r"(r[0]), "=r"(r[1]), "=r"(r[2]), "=r"(r[3]) : "r"(addr));
}
__device__ __forceinline__ void mma16816_(float* d, const uint32_t* a, uint32_t b0, uint32_t b1) {
    asm volatile("mma.sync.aligned.m16n8k16.row.col.f32.bf16.bf16.f32 "
                 "{%0,%1,%2,%3}, {%4,%5,%6,%7}, {%8,%9}, {%0,%1,%2,%3};"
                 : "+f"(d[0]), "+f"(d[1]), "+f"(d[2]), "+f"(d[3])
                 : "r"(a[0]), "r"(a[1]), "r"(a[2]), "r"(a[3]), "r"(b0), "r"(b1));
}

// ============================ mma.sync bf16 2-limb GEMM ============================
// C[M,N] = (Ah+Al)[M,Ka] @ (Bh+Bl)[N,Ka]^T + bias   (drop Al*Bl term)
// Tiles: BM=128, BN=128, BK=32. A rows M mult of 128; B rows padded >= gridX*128; Ka mult of 32.
// CMODE 0: C[m*N + n]; CMODE 1: m = t*128+b -> C[(b*32+t)*300 + n].
// SMEM stage layout (bytes): Ah[128][40]b16 @0, Al @10240, Bh @20480, Bl @30720; stage size 40960.
#define GTS_SMEM (2 * 40960)

template <int CMODE>
__global__ __launch_bounds__(256, 1)
void gemm_ts(const __nv_bfloat16* __restrict__ Ah, const __nv_bfloat16* __restrict__ Al,
             const __nv_bfloat16* __restrict__ Bh, const __nv_bfloat16* __restrict__ Bl,
             const float* __restrict__ bias, float* __restrict__ C,
             int N, int Ka)
{
    extern __shared__ char smem[];
    const uint32_t smb = smem_u32_(smem);
    const int tid = threadIdx.x;
    const int wid = tid >> 5, lane = tid & 31;
    const int wm = wid & 3, wn = wid >> 2;
    const int m0 = blockIdx.y * 128, n0 = blockIdx.x * 128;
    const int nchunk = Ka >> 5;

    // per-thread load coords (2 x 16B per matrix per stage)
    const int lrow0 = tid >> 2,        lg0 = tid & 3;
    const int lrow1 = (tid + 256) >> 2, lg1 = (tid + 256) & 3;

    float acc[2][8][4];
#pragma unroll
    for (int mt = 0; mt < 2; mt++)
#pragma unroll
        for (int nt = 0; nt < 8; nt++)
#pragma unroll
            for (int q = 0; q < 4; q++) acc[mt][nt][q] = 0.0f;

    // ---- prefetch chunk 0 into stage 0 ----
    {
        const uint32_t sb = smb;
        uint32_t o0 = (uint32_t)(lrow0 * 80 + lg0 * 16);
        uint32_t o1 = (uint32_t)(lrow1 * 80 + lg1 * 16);
        cp16_(sb + o0,        Ah + (size_t)(m0 + lrow0) * Ka + lg0 * 8);
        cp16_(sb + o1,        Ah + (size_t)(m0 + lrow1) * Ka + lg1 * 8);
        cp16_(sb + 10240 + o0, Al + (size_t)(m0 + lrow0) * Ka + lg0 * 8);
        cp16_(sb + 10240 + o1, Al + (size_t)(m0 + lrow1) * Ka + lg1 * 8);
        cp16_(sb + 20480 + o0, Bh + (size_t)(n0 + lrow0) * Ka + lg0 * 8);
        cp16_(sb + 20480 + o1, Bh + (size_t)(n0 + lrow1) * Ka + lg1 * 8);
        cp16_(sb + 30720 + o0, Bl + (size_t)(n0 + lrow0) * Ka + lg0 * 8);
        cp16_(sb + 30720 + o1, Bl + (size_t)(n0 + lrow1) * Ka + lg1 * 8);
        cp_commit_();
    }

    for (int c = 0; c < nchunk; ++c) {
        const int s = c & 1;
        cp_wait0_();
        __syncthreads();                       // stage s ready; all compute on s^1 done
        if (c + 1 < nchunk) {                  // prefetch next chunk into other stage
            const int k0 = (c + 1) * 32;
            const uint32_t sb = smb + (uint32_t)((s ^ 1) * 40960);
            uint32_t o0 = (uint32_t)(lrow0 * 80 + lg0 * 16);
            uint32_t o1 = (uint32_t)(lrow1 * 80 + lg1 * 16);
            cp16_(sb + o0,         Ah + (size_t)(m0 + lrow0) * Ka + k0 + lg0 * 8);
            cp16_(sb + o1,         Ah + (size_t)(m0 + lrow1) * Ka + k0 + lg1 * 8);
            cp16_(sb + 10240 + o0, Al + (size_t)(m0 + lrow0) * Ka + k0 + lg0 * 8);
            cp16_(sb + 10240 + o1, Al + (size_t)(m0 + lrow1) * Ka + k0 + lg1 * 8);
            cp16_(sb + 20480 + o0, Bh + (size_t)(n0 + lrow0) * Ka + k0 + lg0 * 8);
            cp16_(sb + 20480 + o1, Bh + (size_t)(n0 + lrow1) * Ka + k0 + lg1 * 8);
            cp16_(sb + 30720 + o0, Bl + (size_t)(n0 + lrow0) * Ka + k0 + lg0 * 8);
            cp16_(sb + 30720 + o1, Bl + (size_t)(n0 + lrow1) * Ka + k0 + lg1 * 8);
            cp_commit_();
        }
        const uint32_t sb = smb + (uint32_t)(s * 40960);
#pragma unroll
        for (int ks = 0; ks < 2; ks++) {
            uint32_t aFh[2][4], aFl[2][4], bFh[4][4], bFl[4][4];
#pragma unroll
            for (int mt = 0; mt < 2; mt++) {
                uint32_t ar = (uint32_t)((wm * 32 + mt * 16 + (lane & 15)) * 80
                                         + ((lane >> 4) * 16) + ks * 32);
                ldm4_(aFh[mt], sb + ar);
                ldm4_(aFl[mt], sb + 10240 + ar);
            }
#pragma unroll
            for (int bt = 0; bt < 4; bt++) {
                uint32_t br = (uint32_t)((wn * 64 + bt * 16 + (lane & 7) + ((lane >> 4) << 3)) * 80
                                         + (((lane >> 3) & 1) * 16) + ks * 32);
                ldm4_(bFh[bt], sb + 20480 + br);
                ldm4_(bFl[bt], sb + 30720 + br);
            }
#pragma unroll
            for (int mt = 0; mt < 2; mt++)
#pragma unroll
                for (int bt = 0; bt < 4; bt++) {
                    mma16816_(acc[mt][2 * bt],     aFh[mt], bFh[bt][0], bFh[bt][1]);
                    mma16816_(acc[mt][2 * bt + 1], aFh[mt], bFh[bt][2], bFh[bt][3]);
                    mma16816_(acc[mt][2 * bt],     aFh[mt], bFl[bt][0], bFl[bt][1]);
                    mma16816_(acc[mt][2 * bt + 1], aFh[mt], bFl[bt][2], bFl[bt][3]);
                    mma16816_(acc[mt][2 * bt],     aFl[mt], bFh[bt][0], bFh[bt][1]);
                    mma16816_(acc[mt][2 * bt + 1], aFl[mt], bFh[bt][2], bFh[bt][3]);
                }
        }
        __syncthreads();                       // done reading stage s before it is refilled
    }

    // ---- epilogue: acc -> gmem with bias ----
#pragma unroll
    for (int mt = 0; mt < 2; mt++) {
        int r0 = m0 + wm * 32 + mt * 16 + (lane >> 2);
        int r1 = r0 + 8;
#pragma unroll
        for (int nt = 0; nt < 8; nt++) {
            int n = n0 + wn * 64 + nt * 8 + 2 * (lane & 3);
            if (n < N) {
                float b0 = bias ? bias[n] : 0.0f;
                float b1 = bias ? bias[n + 1] : 0.0f;
                float2 v0 = make_float2(acc[mt][nt][0] + b0, acc[mt][nt][1] + b1);
                float2 v1 = make_float2(acc[mt][nt][2] + b0, acc[mt][nt][3] + b1);
                if (CMODE == 0) {
                    *(float2*)(C + (size_t)r0 * N + n) = v0;
                    *(float2*)(C + (size_t)r1 * N + n) = v1;
                } else {
                    *(float2*)(C + (size_t)((r0 & 127) * T_DEC + (r0 >> 7)) * D_W + n) = v0;
                    *(float2*)(C + (size_t)((r1 & 127) * T_DEC + (r1 >> 7)) * D_W + n) = v1;
                }
            }
        }
    }
}

// ============================ conversion kernels ============================
__device__ __forceinline__ void split_bf16_(float x, __nv_bfloat16* h, __nv_bfloat16* l) {
    __nv_bfloat16 hi = __float2bfloat16(x);
    *h = hi;
    *l = __float2bfloat16(x - __bfloat162float(hi));
}

// frames [B,T_enc,D] -> A rows m=t*128+b, bf16 hi/lo
__global__ void conv_frames(const float* __restrict__ frames,
                            __nv_bfloat16* __restrict__ Ah, __nv_bfloat16* __restrict__ Al)
{
    int m = blockIdx.x;
    int b = m & 127, t = m >> 7;
    const float* src = frames + (size_t)(b * T_ENC + t) * D_IN;
    size_t dst = (size_t)m * D_IN;
    for (int k = threadIdx.x; k < D_IN; k += blockDim.x)
        split_bf16_(src[k], &Ah[dst + k], &Al[dst + k]);
}

// W[Ksrc, ldw] -> transposed bf16 hi/lo [Npad, Kpad] (zero-padded)
__global__ void conv_w_t(const float* __restrict__ W, int ldw, int Ksrc, int Kpad, int Nsrc,
                         __nv_bfloat16* __restrict__ Th, __nv_bfloat16* __restrict__ Tl)
{
    __shared__ float s[32][33];
    int k0 = blockIdx.x * 32, n0 = blockIdx.y * 32;
    int tx = threadIdx.x, ty = threadIdx.y;   // 32 x 8
#pragma unroll
    for (int j = 0; j < 4; j++) {
        int k = k0 + ty + j * 8, n = n0 + tx;
        s[ty + j * 8][tx] = (k < Ksrc && n < Nsrc) ? W[(size_t)k * ldw + n] : 0.0f;
    }
    __syncthreads();
#pragma unroll
    for (int j = 0; j < 4; j++) {
        int n = n0 + ty + j * 8, k = k0 + tx;
        split_bf16_(s[tx][ty + j * 8], &Th[(size_t)n * Kpad + k], &Tl[(size_t)n * Kpad + k]);
    }
}

// caption embeddings gathered + bf16 split, row m=t*128+b, K padded to 320
__global__ void gather_conv(const int* __restrict__ ids, const float* __restrict__ emb,
                            __nv_bfloat16* __restrict__ Ah, __nv_bfloat16* __restrict__ Al)
{
    int m = blockIdx.x;
    int t = m >> 7, b = m & 127;
    int id = ids[b * T_DEC + t];
    const float* src = emb + (size_t)id * D_W;
    size_t dst = (size_t)m * D_WP;
    for (int k = threadIdx.x; k < D_WP; k += blockDim.x) {
        float x = (k < D_W) ? src[k] : 0.0f;
        split_bf16_(x, &Ah[dst + k], &Al[dst + k]);
    }
}

// ============================ fused recurrent step ============================
// GEMM partial (hin @ Wh chunk) + last-CTA-of-4 reduce + LSTM pointwise -> hout.
// hin/hout are distinct ping-pong buffers. Grid (16, 2, 4), 256 threads.
__global__ __launch_bounds__(256)
void lstm_step(const float* __restrict__ Wh, const float* __restrict__ Xg,
               const float* __restrict__ hin, float* __restrict__ hout,
               int* __restrict__ cnt,
               __nv_bfloat16* __restrict__ dh, __nv_bfloat16* __restrict__ dl)
{
    const int u0 = blockIdx.x * 32;
    const int r0 = blockIdx.y * 64;
    const int ks = blockIdx.z;
    const int k0 = ks * 128;

    __shared__ float Hs[32][68];
    __shared__ float Ws[32][128];
    __shared__ int s_old;

    const int tid = threadIdx.x;
    const int hx = tid & 31;
    const int rg = tid >> 5;
    const int lr = tid >> 2;
    const int lk = (tid & 3) * 8;

    float acc[8][4];
#pragma unroll
    for (int i = 0; i < 8; i++)
#pragma unroll
        for (int g = 0; g < 4; g++) acc[i][g] = 0.0f;

    for (int kc = 0; kc < 4; ++kc) {
        const int kb = k0 + kc * 32;
        {
            const float* hp = hin + (size_t)(r0 + lr) * H_SZ + kb + lk;
            float4 v0 = *(const float4*)hp;
            float4 v1 = *(const float4*)(hp + 4);
            Hs[lk + 0][lr] = v0.x; Hs[lk + 1][lr] = v0.y;
            Hs[lk + 2][lr] = v0.z; Hs[lk + 3][lr] = v0.w;
            Hs[lk + 4][lr] = v1.x; Hs[lk + 5][lr] = v1.y;
            Hs[lk + 6][lr] = v1.z; Hs[lk + 7][lr] = v1.w;
        }
#pragma unroll
        for (int it = 0; it < 4; ++it) {
            int f = it * 1024 + tid * 4;
            int kk = f >> 7;
            int c = f & 127;
            int g = c >> 5;
            int hh = c & 31;
            float4 w = *(const float4*)(Wh + (size_t)(kb + kk) * G4 + g * H_SZ + u0 + hh);
            *(float4*)&Ws[kk][c] = w;
        }
        __syncthreads();
#pragma unroll
        for (int kk = 0; kk < 32; ++kk) {
            float a[8];
            *(float4*)(a)     = *(const float4*)&Hs[kk][rg * 8];
            *(float4*)(a + 4) = *(const float4*)&Hs[kk][rg * 8 + 4];
            float w0 = Ws[kk][hx];
            float w1 = Ws[kk][32 + hx];
            float w2 = Ws[kk][64 + hx];
            float w3 = Ws[kk][96 + hx];
#pragma unroll
            for (int i = 0; i < 8; i++) {
                acc[i][0] = fmaf(a[i], w0, acc[i][0]);
                acc[i][1] = fmaf(a[i], w1, acc[i][1]);
                acc[i][2] = fmaf(a[i], w2, acc[i][2]);
                acc[i][3] = fmaf(a[i], w3, acc[i][3]);
            }
        }
        __syncthreads();
    }

    float* pp = g_P + (size_t)ks * (B_SZ * G4);
#pragma unroll
    for (int i = 0; i < 8; i++) {
        int row = r0 + rg * 8 + i;
#pragma unroll
        for (int g = 0; g < 4; g++)
            pp[(size_t)row * G4 + g * H_SZ + u0 + hx] = acc[i][g];
    }

    __threadfence();
    __syncthreads();
    if (tid == 0) s_old = atomicAdd(&cnt[blockIdx.y * 16 + blockIdx.x], 1);
    __syncthreads();
    if (s_old != 3) return;
    __threadfence();
    if (tid == 0) cnt[blockIdx.y * 16 + blockIdx.x] = 0;   // reset for next replay

    // last CTA: reduce 4 partials + pointwise for tile (r0..r0+63, u0..u0+31)
    const int u = u0 + hx;
#pragma unroll
    for (int i = 0; i < 8; i++) {
        int b = r0 + rg * 8 + i;
        size_t base = (size_t)b * G4 + u;
        float gi = Xg[base];
        float gj = Xg[base + H_SZ];
        float gf = Xg[base + 2 * H_SZ];
        float go = Xg[base + 3 * H_SZ];
#pragma unroll
        for (int s = 0; s < 4; s++) {
            const float* p = g_P + (size_t)s * (B_SZ * G4) + base;
            gi += p[0]; gj += p[H_SZ]; gf += p[2 * H_SZ]; go += p[3 * H_SZ];
        }
        int hidx = b * H_SZ + u;
        float cn = g_c[hidx] * sigmoidf_(gf + 1.0f) + sigmoidf_(gi) * tanhf(gj);
        float hn = tanhf(cn) * sigmoidf_(go);
        g_c[hidx] = cn;
        hout[hidx] = hn;
        if (dh) split_bf16_(hn, &dh[hidx], &dl[hidx]);
    }
}

// ---------------- first step (h=0, c=0): gates = Xg only ----------------
__global__ __launch_bounds__(256)
void lstm_first(const float* __restrict__ Xg, float* __restrict__ hout)
{
    int idx = blockIdx.x * blockDim.x + threadIdx.x;
    if (idx >= B_SZ * H_SZ) return;
    int b = idx >> 9;
    int u = idx & (H_SZ - 1);
    const float* xg = Xg + (size_t)b * G4;
    float gi = xg[u], gj = xg[H_SZ + u], go = xg[3 * H_SZ + u];
    float cn = sigmoidf_(gi) * tanhf(gj);   // cprev=0
    float hn = tanhf(cn) * sigmoidf_(go);
    g_c[idx] = cn;
    hout[idx] = hn;
}

// ============================ host launcher ============================
extern "C" void kernel_launch(void* const* d_in, const int* in_sizes, int n_in,
                              void* d_out, int out_size)
{
    (void)in_sizes; (void)n_in; (void)out_size;
    const float* frames = (const float*)d_in[0];
    const int*   ids    = (const int*)d_in[1];
    const float* emb    = (const float*)d_in[2];
    const float* W_enc  = (const float*)d_in[3];
    const float* b_enc  = (const float*)d_in[4];
    const float* W_dec  = (const float*)d_in[5];
    const float* b_dec  = (const float*)d_in[6];
    const float* W_out  = (const float*)d_in[7];
    const float* b_out  = (const float*)d_in[8];
    float* out = (float*)d_out;

    float *Xge, *Xgd, *hb; int* cnt;
    __nv_bfloat16 *Afh, *Afl, *Beh, *Bel, *Adh, *Adl, *Bdh, *Bdl, *Dhh, *Dhl, *Boh, *Bol;
    cudaGetSymbolAddress((void**)&Xge, g_Xg_enc);
    cudaGetSymbolAddress((void**)&Xgd, g_Xg_dec);
    cudaGetSymbolAddress((void**)&hb,  g_hbuf);
    cudaGetSymbolAddress((void**)&cnt, g_cnt);
    cudaGetSymbolAddress((void**)&Afh, g_Afr_h);  cudaGetSymbolAddress((void**)&Afl, g_Afr_l);
    cudaGetSymbolAddress((void**)&Beh, g_Bte_h);  cudaGetSymbolAddress((void**)&Bel, g_Bte_l);
    cudaGetSymbolAddress((void**)&Adh, g_Ad_h);   cudaGetSymbolAddress((void**)&Adl, g_Ad_l);
    cudaGetSymbolAddress((void**)&Bdh, g_Btd_h);  cudaGetSymbolAddress((void**)&Bdl, g_Btd_l);
    cudaGetSymbolAddress((void**)&Dhh, g_Dh_h);   cudaGetSymbolAddress((void**)&Dhl, g_Dh_l);
    cudaGetSymbolAddress((void**)&Boh, g_Bto_h);  cudaGetSymbolAddress((void**)&Bol, g_Bto_l);

    float* hbuf0 = hb;
    float* hbuf1 = hb + B_SZ * H_SZ;

    cudaFuncSetAttribute(gemm_ts<0>, cudaFuncAttributeMaxDynamicSharedMemorySize, GTS_SMEM);
    cudaFuncSetAttribute(gemm_ts<1>, cudaFuncAttributeMaxDynamicSharedMemorySize, GTS_SMEM);

    // conversions
    conv_frames<<<M_ENC, 256>>>(frames, Afh, Afl);
    conv_w_t<<<dim3(D_IN / 32, G4 / 32), dim3(32, 8)>>>(W_enc, G4, D_IN, D_IN, G4, Beh, Bel);
    conv_w_t<<<dim3(D_WP / 32, G4 / 32), dim3(32, 8)>>>(W_dec, G4, D_W, D_WP, G4, Bdh, Bdl);
    conv_w_t<<<dim3(H_SZ / 32, 512 / 32), dim3(32, 8)>>>(W_out, D_W, H_SZ, H_SZ, D_W, Boh, Bol);
    gather_conv<<<M_DEC, 128>>>(ids, emb, Adh, Adl);

    // 1. Encoder input gates: [8192,2048] @ [2048,2048]^T + b_enc
    gemm_ts<0><<<dim3(G4 / 128, M_ENC / 128), 256, GTS_SMEM>>>(
        Afh, Afl, Beh, Bel, b_enc, Xge, G4, D_IN);

    // 2. Encoder recurrence (ping-pong h buffers)
    const float* Wh_enc = W_enc + (size_t)D_IN * G4;
    int cur = 0;
    lstm_first<<<(B_SZ * H_SZ) / 256, 256>>>(Xge, hbuf0);
    for (int t = 1; t < T_ENC; ++t) {
        float* hin  = cur ? hbuf1 : hbuf0;
        float* hout = cur ? hbuf0 : hbuf1;
        lstm_step<<<dim3(16, 2, 4), 256>>>(Wh_enc, Xge + (size_t)t * B_SZ * G4,
                                           hin, hout, cnt + (t - 1) * 32, nullptr, nullptr);
        cur ^= 1;
    }

    // 3. Decoder input gates: [4096,320] @ [2048,320]^T + b_dec
    gemm_ts<0><<<dim3(G4 / 128, M_DEC / 128), 256, GTS_SMEM>>>(
        Adh, Adl, Bdh, Bdl, b_dec, Xgd, G4, D_WP);

    // 4. Decoder recurrence (starts from encoder state), writes h limbs
    const float* Wh_dec = W_dec + (size_t)D_W * G4;
    for (int t = 0; t < T_DEC; ++t) {
        float* hin  = cur ? hbuf1 : hbuf0;
        float* hout = cur ? hbuf0 : hbuf1;
        lstm_step<<<dim3(16, 2, 4), 256>>>(Wh_dec, Xgd + (size_t)t * B_SZ * G4,
                                           hin, hout, cnt + (T_ENC - 1 + t) * 32,
                                           Dhh + (size_t)t * B_SZ * H_SZ,
                                           Dhl + (size_t)t * B_SZ * H_SZ);
        cur ^= 1;
    }

    // 5. Output projection: [4096,512] @ [512(pad of 300),512]^T + b_out, permuted store
    gemm_ts<1><<<dim3(3, M_DEC / 128), 256, GTS_SMEM>>>(
        Dhh, Dhl, Boh, Bol, b_out, out, D_W, H_SZ);
}

// round 6
// speedup vs baseline: 2.1031x; 1.6385x over previous
#include <cuda_runtime.h>
#include <cuda_bf16.h>
#include <math.h>
#include <stdint.h>

// Problem constants
#define B_SZ   128
#define T_ENC  64
#define D_IN   2048
#define T_DEC  32
#define D_W    300
#define D_WP   320
#define H_SZ   512
#define G4     2048
#define M_ENC  (T_ENC * B_SZ)   // 8192
#define M_DEC  (T_DEC * B_SZ)   // 4096

// ---------------- scratch (device globals; no allocation) ----------------
__device__ float g_Xg_enc[(size_t)M_ENC * G4];
__device__ float g_Xg_dec[(size_t)M_DEC * G4];
__device__ float g_P    [4 * B_SZ * G4];     // split-K partials, gate-interleaved cols (u*4+g)
__device__ float g_c    [B_SZ * H_SZ];
__device__ unsigned g_bar;                   // monotonic grid-barrier counter (128 | 2^32)

// bf16 limb arrays (16B aligned)
__device__ __align__(16) __nv_bfloat16 g_hl  [2][2][B_SZ * H_SZ];     // [parity][limb] recurrent h
__device__ __align__(16) __nv_bfloat16 g_WhT [2][2][(size_t)G4 * H_SZ]; // [enc/dec][limb] Wh^T rows u*4+g
__device__ __align__(16) __nv_bfloat16 g_Afr_h[(size_t)M_ENC * D_IN];
__device__ __align__(16) __nv_bfloat16 g_Afr_l[(size_t)M_ENC * D_IN];
__device__ __align__(16) __nv_bfloat16 g_Bte_h[(size_t)G4 * D_IN];
__device__ __align__(16) __nv_bfloat16 g_Bte_l[(size_t)G4 * D_IN];
__device__ __align__(16) __nv_bfloat16 g_Ad_h [(size_t)M_DEC * D_WP];
__device__ __align__(16) __nv_bfloat16 g_Ad_l [(size_t)M_DEC * D_WP];
__device__ __align__(16) __nv_bfloat16 g_Btd_h[(size_t)G4 * D_WP];
__device__ __align__(16) __nv_bfloat16 g_Btd_l[(size_t)G4 * D_WP];
__device__ __align__(16) __nv_bfloat16 g_Dh_h [(size_t)M_DEC * H_SZ];
__device__ __align__(16) __nv_bfloat16 g_Dh_l [(size_t)M_DEC * H_SZ];
__device__ __align__(16) __nv_bfloat16 g_Bto_h[(size_t)512 * H_SZ];
__device__ __align__(16) __nv_bfloat16 g_Bto_l[(size_t)512 * H_SZ];

__device__ __forceinline__ float sigmoidf_(float x) { return 1.0f / (1.0f + expf(-x)); }

// ============================ PTX helpers (baseline ISA) ============================
__device__ __forceinline__ uint32_t smem_u32_(const void* p) {
    uint32_t a;
    asm("{ .reg .u64 t; cvta.to.shared.u64 t, %1; cvt.u32.u64 %0, t; }" : "=r"(a) : "l"(p));
    return a;
}
__device__ __forceinline__ void cp16_(uint32_t dst, const void* src) {
    asm volatile("cp.async.cg.shared.global [%0], [%1], 16;" :: "r"(dst), "l"(src));
}
__device__ __forceinline__ void cp_commit_() { asm volatile("cp.async.commit_group;" ::: "memory"); }
__device__ __forceinline__ void cp_wait0_()  { asm volatile("cp.async.wait_group 0;" ::: "memory"); }
__device__ __forceinline__ void cp_wait1_()  { asm volatile("cp.async.wait_group 1;" ::: "memory"); }

__device__ __forceinline__ void ldm4_(uint32_t* r, uint32_t addr) {
    asm volatile("ldmatrix.sync.aligned.m8n8.x4.shared.b16 {%0,%1,%2,%3}, [%4];"
                 : "=r"(r[0]), "=r"(r[1]), "=r"(r[2]), "=r"(r[3]) : "r"(addr));
}
__device__ __forceinline__ void mma16816_(float* d, const uint32_t* a, uint32_t b0, uint32_t b1) {
    asm volatile("mma.sync.aligned.m16n8k16.row.col.f32.bf16.bf16.f32 "
                 "{%0,%1,%2,%3}, {%4,%5,%6,%7}, {%8,%9}, {%0,%1,%2,%3};"
                 : "+f"(d[0]), "+f"(d[1]), "+f"(d[2]), "+f"(d[3])
                 : "r"(a[0]), "r"(a[1]), "r"(a[2]), "r"(a[3]), "r"(b0), "r"(b1));
}

// grid-wide barrier for 128 co-resident CTAs; monotonic counter, replay-safe.
__device__ __forceinline__ void grid_bar_() {
    __threadfence();
    __syncthreads();
    if (threadIdx.x == 0) {
        unsigned old = atomicAdd(&g_bar, 1u);
        unsigned target = ((old >> 7) + 1u) << 7;
        while ((int)(target - *((volatile unsigned*)&g_bar)) > 0) {}
    }
    __syncthreads();
}

// ============================ mma.sync bf16 2-limb GEMM (3-stage) ============================
// C[M,N] = (Ah+Al)[M,Ka] @ (Bh+Bl)[N,Ka]^T + bias  (drop Al*Bl).
// BM=128, BN=128, BK=32, 3 cp.async stages. Stage: Ah@0 Al@10240 Bh@20480 Bl@30720 (row stride 80B).
#define GTS_SMEM (3 * 40960)

__device__ __forceinline__ void gts_pf_(uint32_t sb,
    const __nv_bfloat16* Ah, const __nv_bfloat16* Al,
    const __nv_bfloat16* Bh, const __nv_bfloat16* Bl,
    int m0, int n0, int k0, int Ka, int lrow0, int lg0, int lrow1, int lg1)
{
    uint32_t o0 = (uint32_t)(lrow0 * 80 + lg0 * 16);
    uint32_t o1 = (uint32_t)(lrow1 * 80 + lg1 * 16);
    cp16_(sb + o0,         Ah + (size_t)(m0 + lrow0) * Ka + k0 + lg0 * 8);
    cp16_(sb + o1,         Ah + (size_t)(m0 + lrow1) * Ka + k0 + lg1 * 8);
    cp16_(sb + 10240 + o0, Al + (size_t)(m0 + lrow0) * Ka + k0 + lg0 * 8);
    cp16_(sb + 10240 + o1, Al + (size_t)(m0 + lrow1) * Ka + k0 + lg1 * 8);
    cp16_(sb + 20480 + o0, Bh + (size_t)(n0 + lrow0) * Ka + k0 + lg0 * 8);
    cp16_(sb + 20480 + o1, Bh + (size_t)(n0 + lrow1) * Ka + k0 + lg1 * 8);
    cp16_(sb + 30720 + o0, Bl + (size_t)(n0 + lrow0) * Ka + k0 + lg0 * 8);
    cp16_(sb + 30720 + o1, Bl + (size_t)(n0 + lrow1) * Ka + k0 + lg1 * 8);
    cp_commit_();
}

template <int CMODE>
__global__ __launch_bounds__(256, 1)
void gemm_ts(const __nv_bfloat16* __restrict__ Ah, const __nv_bfloat16* __restrict__ Al,
             const __nv_bfloat16* __restrict__ Bh, const __nv_bfloat16* __restrict__ Bl,
             const float* __restrict__ bias, float* __restrict__ C,
             int N, int Ka)
{
    extern __shared__ char smem[];
    const uint32_t smb = smem_u32_(smem);
    const int tid = threadIdx.x;
    const int wid = tid >> 5, lane = tid & 31;
    const int wm = wid & 3, wn = wid >> 2;
    const int m0 = blockIdx.y * 128, n0 = blockIdx.x * 128;
    const int nchunk = Ka >> 5;

    const int lrow0 = tid >> 2,         lg0 = tid & 3;
    const int lrow1 = (tid + 256) >> 2, lg1 = (tid + 256) & 3;

    float acc[2][8][4];
#pragma unroll
    for (int mt = 0; mt < 2; mt++)
#pragma unroll
        for (int nt = 0; nt < 8; nt++)
#pragma unroll
            for (int q = 0; q < 4; q++) acc[mt][nt][q] = 0.0f;

    gts_pf_(smb,         Ah, Al, Bh, Bl, m0, n0, 0,  Ka, lrow0, lg0, lrow1, lg1);
    gts_pf_(smb + 40960, Ah, Al, Bh, Bl, m0, n0, 32, Ka, lrow0, lg0, lrow1, lg1);

    for (int c = 0; c < nchunk; ++c) {
        if (c + 1 < nchunk) cp_wait1_(); else cp_wait0_();
        __syncthreads();
        if (c + 2 < nchunk)
            gts_pf_(smb + (uint32_t)(((c + 2) % 3) * 40960),
                    Ah, Al, Bh, Bl, m0, n0, (c + 2) * 32, Ka, lrow0, lg0, lrow1, lg1);
        const uint32_t sb = smb + (uint32_t)((c % 3) * 40960);
#pragma unroll
        for (int ks = 0; ks < 2; ks++) {
            uint32_t aFh[2][4], aFl[2][4], bFh[4][4], bFl[4][4];
#pragma unroll
            for (int mt = 0; mt < 2; mt++) {
                uint32_t ar = (uint32_t)((wm * 32 + mt * 16 + (lane & 15)) * 80
                                         + ((lane >> 4) * 16) + ks * 32);
                ldm4_(aFh[mt], sb + ar);
                ldm4_(aFl[mt], sb + 10240 + ar);
            }
#pragma unroll
            for (int bt = 0; bt < 4; bt++) {
                uint32_t br = (uint32_t)((wn * 64 + bt * 16 + (lane & 7) + ((lane >> 4) << 3)) * 80
                                         + (((lane >> 3) & 1) * 16) + ks * 32);
                ldm4_(bFh[bt], sb + 20480 + br);
                ldm4_(bFl[bt], sb + 30720 + br);
            }
            // pass 1: Ah*Bh (16 independent MMAs)
#pragma unroll
            for (int mt = 0; mt < 2; mt++)
#pragma unroll
                for (int bt = 0; bt < 4; bt++) {
                    mma16816_(acc[mt][2 * bt],     aFh[mt], bFh[bt][0], bFh[bt][1]);
                    mma16816_(acc[mt][2 * bt + 1], aFh[mt], bFh[bt][2], bFh[bt][3]);
                }
            // pass 2: Ah*Bl
#pragma unroll
            for (int mt = 0; mt < 2; mt++)
#pragma unroll
                for (int bt = 0; bt < 4; bt++) {
                    mma16816_(acc[mt][2 * bt],     aFh[mt], bFl[bt][0], bFl[bt][1]);
                    mma16816_(acc[mt][2 * bt + 1], aFh[mt], bFl[bt][2], bFl[bt][3]);
                }
            // pass 3: Al*Bh
#pragma unroll
            for (int mt = 0; mt < 2; mt++)
#pragma unroll
                for (int bt = 0; bt < 4; bt++) {
                    mma16816_(acc[mt][2 * bt],     aFl[mt], bFh[bt][0], bFh[bt][1]);
                    mma16816_(acc[mt][2 * bt + 1], aFl[mt], bFh[bt][2], bFh[bt][3]);
                }
        }
        __syncthreads();
    }

#pragma unroll
    for (int mt = 0; mt < 2; mt++) {
        int r0 = m0 + wm * 32 + mt * 16 + (lane >> 2);
        int r1 = r0 + 8;
#pragma unroll
        for (int nt = 0; nt < 8; nt++) {
            int n = n0 + wn * 64 + nt * 8 + 2 * (lane & 3);
            if (n < N) {
                float b0 = bias ? bias[n] : 0.0f;
                float b1 = bias ? bias[n + 1] : 0.0f;
                float2 v0 = make_float2(acc[mt][nt][0] + b0, acc[mt][nt][1] + b1);
                float2 v1 = make_float2(acc[mt][nt][2] + b0, acc[mt][nt][3] + b1);
                if (CMODE == 0) {
                    *(float2*)(C + (size_t)r0 * N + n) = v0;
                    *(float2*)(C + (size_t)r1 * N + n) = v1;
                } else {
                    *(float2*)(C + (size_t)((r0 & 127) * T_DEC + (r0 >> 7)) * D_W + n) = v0;
                    *(float2*)(C + (size_t)((r1 & 127) * T_DEC + (r1 >> 7)) * D_W + n) = v1;
                }
            }
        }
    }
}

// ============================ conversion kernels ============================
__device__ __forceinline__ void split_bf16_(float x, __nv_bfloat16* h, __nv_bfloat16* l) {
    __nv_bfloat16 hi = __float2bfloat16(x);
    *h = hi;
    *l = __float2bfloat16(x - __bfloat162float(hi));
}

__global__ void conv_frames(const float* __restrict__ frames,
                            __nv_bfloat16* __restrict__ Ah, __nv_bfloat16* __restrict__ Al)
{
    int m = blockIdx.x;
    int b = m & 127, t = m >> 7;
    const float* src = frames + (size_t)(b * T_ENC + t) * D_IN;
    size_t dst = (size_t)m * D_IN;
    for (int k = threadIdx.x; k < D_IN; k += blockDim.x)
        split_bf16_(src[k], &Ah[dst + k], &Al[dst + k]);
}

__global__ void conv_w_t(const float* __restrict__ W, int ldw, int Ksrc, int Kpad, int Nsrc,
                         __nv_bfloat16* __restrict__ Th, __nv_bfloat16* __restrict__ Tl)
{
    __shared__ float s[32][33];
    int k0 = blockIdx.x * 32, n0 = blockIdx.y * 32;
    int tx = threadIdx.x, ty = threadIdx.y;
#pragma unroll
    for (int j = 0; j < 4; j++) {
        int k = k0 + ty + j * 8, n = n0 + tx;
        s[ty + j * 8][tx] = (k < Ksrc && n < Nsrc) ? W[(size_t)k * ldw + n] : 0.0f;
    }
    __syncthreads();
#pragma unroll
    for (int j = 0; j < 4; j++) {
        int n = n0 + ty + j * 8, k = k0 + tx;
        split_bf16_(s[tx][ty + j * 8], &Th[(size_t)n * Kpad + k], &Tl[(size_t)n * Kpad + k]);
    }
}

// Wh [512 k][2048 cols (g*512+u)] -> WhT limbs [2048 rows (u*4+g)][512 k]
__global__ void conv_whT(const float* __restrict__ Wh,
                         __nv_bfloat16* __restrict__ Th, __nv_bfloat16* __restrict__ Tl)
{
    __shared__ float s[32][33];
    int k0 = blockIdx.x * 32, u0 = blockIdx.y * 32, g = blockIdx.z;
    int tx = threadIdx.x, ty = threadIdx.y;
#pragma unroll
    for (int j = 0; j < 4; j++) {
        int k = k0 + ty + j * 8;
        s[ty + j * 8][tx] = Wh[(size_t)k * G4 + g * H_SZ + u0 + tx];
    }
    __syncthreads();
#pragma unroll
    for (int j = 0; j < 4; j++) {
        int u = u0 + ty + j * 8;
        int r = u * 4 + g;
        split_bf16_(s[tx][ty + j * 8], &Th[(size_t)r * H_SZ + k0 + tx],
                                       &Tl[(size_t)r * H_SZ + k0 + tx]);
    }
}

__global__ void gather_conv(const int* __restrict__ ids, const float* __restrict__ emb,
                            __nv_bfloat16* __restrict__ Ah, __nv_bfloat16* __restrict__ Al)
{
    int m = blockIdx.x;
    int t = m >> 7, b = m & 127;
    int id = ids[b * T_DEC + t];
    const float* src = emb + (size_t)id * D_W;
    size_t dst = (size_t)m * D_WP;
    for (int k = threadIdx.x; k < D_WP; k += blockDim.x) {
        float x = (k < D_W) ? src[k] : 0.0f;
        split_bf16_(x, &Ah[dst + k], &Al[dst + k]);
    }
}

// ============================ persistent tensor-core recurrence ============================
// grid (32,1,4) = 128 CTAs (co-resident). CTA (bx,ks): C tile = all 128 rows x 64 WhT-rows
// [bx*64..), K chunk ks*128. B (WhT limbs) resident in smem across all steps.
// Per step: stage h limbs (cp.async.cg), 192 MMAs/warp, write P, grid bar, distributed
// pointwise (CTA cid owns batch b=cid), grid bar, swap h parity.
#define REC_SMEM (2 * 17408 + 2 * 34816)

__global__ __launch_bounds__(256, 1)
void lstm_rec(const __nv_bfloat16* __restrict__ WTh, const __nv_bfloat16* __restrict__ WTl,
              const float* __restrict__ Xg0, int nsteps, int do_first,
              const __nv_bfloat16* inh, const __nv_bfloat16* inl,
              __nv_bfloat16* outh, __nv_bfloat16* outl,
              __nv_bfloat16* dh, __nv_bfloat16* dl)
{
    extern __shared__ char dsm[];
    const uint32_t Bsb = smem_u32_(dsm);                 // 2 limbs x 64 rows x 272B
    const uint32_t Asb = Bsb + 2 * 17408;                // 2 limbs x 128 rows x 272B
    const int tid = threadIdx.x;
    const int w = tid >> 5, lane = tid & 31;
    const int bx = blockIdx.x;
    const int ks = blockIdx.z;
    const int k0 = ks * 128;
    const int cid = ks * 32 + bx;
    const int n0row = bx * 64;

    // preload B limbs once
    {
        int row = tid >> 2;
#pragma unroll
        for (int i = 0; i < 4; i++) {
            int j = (tid & 3) * 4 + i;
            cp16_(Bsb + row * 272 + j * 16,         WTh + (size_t)(n0row + row) * H_SZ + k0 + j * 8);
            cp16_(Bsb + 17408 + row * 272 + j * 16, WTl + (size_t)(n0row + row) * H_SZ + k0 + j * 8);
        }
        cp_commit_(); cp_wait0_();
    }
    __syncthreads();

    const __nv_bfloat16* hin_h = inh; const __nv_bfloat16* hin_l = inl;
    __nv_bfloat16* hout_h = outh;     __nv_bfloat16* hout_l = outl;

    int tstart = 0;
    if (do_first) {   // step 0: pointwise only (h=0, c=0)
        const float* Xgt = Xg0 + (size_t)cid * G4;
#pragma unroll
        for (int e = 0; e < 2; e++) {
            int u = tid + e * 256;
            float gi = Xgt[u], gj = Xgt[512 + u], go = Xgt[1536 + u];
            float cn = sigmoidf_(gi) * tanhf(gj);
            float hn = tanhf(cn) * sigmoidf_(go);
            int hidx = cid * H_SZ + u;
            g_c[hidx] = cn;
            split_bf16_(hn, &hout_h[hidx], &hout_l[hidx]);
        }
        grid_bar_();
        const __nv_bfloat16* th = hout_h; const __nv_bfloat16* tl = hout_l;
        hout_h = (__nv_bfloat16*)hin_h; hout_l = (__nv_bfloat16*)hin_l;
        hin_h = th; hin_l = tl;
        tstart = 1;
    }

    for (int t = tstart; t < nsteps; ++t) {
        // stage A (h limbs), this CTA's K chunk, via L2 (cp.async.cg)
        {
            int row = tid >> 1;
#pragma unroll
            for (int i = 0; i < 8; i++) {
                int j = (tid & 1) * 8 + i;
                cp16_(Asb + row * 272 + j * 16,         hin_h + (size_t)row * H_SZ + k0 + j * 8);
                cp16_(Asb + 34816 + row * 272 + j * 16, hin_l + (size_t)row * H_SZ + k0 + j * 8);
            }
            cp_commit_(); cp_wait0_();
        }
        __syncthreads();

        float acc[8][4];
#pragma unroll
        for (int nt = 0; nt < 8; nt++)
#pragma unroll
            for (int q = 0; q < 4; q++) acc[nt][q] = 0.0f;

#pragma unroll
        for (int kk = 0; kk < 8; kk++) {
            uint32_t aFh[4], aFl[4], bFh[4][4], bFl[4][4];
            uint32_t ar = Asb + (uint32_t)((w * 16 + (lane & 15)) * 272 + kk * 32 + ((lane >> 4) << 4));
            ldm4_(aFh, ar);
            ldm4_(aFl, ar + 34816);
#pragma unroll
            for (int bt = 0; bt < 4; bt++) {
                uint32_t br = Bsb + (uint32_t)((bt * 16 + (lane & 7) + ((lane >> 4) << 3)) * 272
                                               + (((lane >> 3) & 1) << 4) + kk * 32);
                ldm4_(bFh[bt], br);
                ldm4_(bFl[bt], br + 17408);
            }
#pragma unroll
            for (int bt = 0; bt < 4; bt++) {
                mma16816_(acc[2 * bt],     aFh, bFh[bt][0], bFh[bt][1]);
                mma16816_(acc[2 * bt + 1], aFh, bFh[bt][2], bFh[bt][3]);
            }
#pragma unroll
            for (int bt = 0; bt < 4; bt++) {
                mma16816_(acc[2 * bt],     aFh, bFl[bt][0], bFl[bt][1]);
                mma16816_(acc[2 * bt + 1], aFh, bFl[bt][2], bFl[bt][3]);
            }
#pragma unroll
            for (int bt = 0; bt < 4; bt++) {
                mma16816_(acc[2 * bt],     aFl, bFh[bt][0], bFh[bt][1]);
                mma16816_(acc[2 * bt + 1], aFl, bFh[bt][2], bFh[bt][3]);
            }
        }
        __syncthreads();

        // write P partials (cols gate-interleaved: n_global = u*4+g)
        {
            int r0w = w * 16 + (lane >> 2);
            float* pp = g_P + (size_t)ks * (B_SZ * G4);
#pragma unroll
            for (int nt = 0; nt < 8; nt++) {
                int n = n0row + nt * 8 + (lane & 3) * 2;
                *(float2*)(pp + (size_t)r0w * G4 + n)       = make_float2(acc[nt][0], acc[nt][1]);
                *(float2*)(pp + (size_t)(r0w + 8) * G4 + n) = make_float2(acc[nt][2], acc[nt][3]);
            }
        }
        grid_bar_();

        // distributed pointwise: CTA cid owns batch b=cid
        {
            const float* Xgt = Xg0 + (size_t)t * (B_SZ * G4) + (size_t)cid * G4;
#pragma unroll
            for (int e = 0; e < 2; e++) {
                int u = tid + e * 256;
                float gi = Xgt[u], gj = Xgt[512 + u], gf = Xgt[1024 + u], go = Xgt[1536 + u];
                size_t pb = (size_t)cid * G4 + (size_t)u * 4;
#pragma unroll
                for (int s = 0; s < 4; s++) {
                    float4 q = __ldcg((const float4*)(g_P + (size_t)s * (B_SZ * G4) + pb));
                    gi += q.x; gj += q.y; gf += q.z; go += q.w;
                }
                int hidx = cid * H_SZ + u;
                float cn = g_c[hidx] * sigmoidf_(gf + 1.0f) + sigmoidf_(gi) * tanhf(gj);
                float hn = tanhf(cn) * sigmoidf_(go);
                g_c[hidx] = cn;
                __nv_bfloat16 hh = __float2bfloat16(hn);
                __nv_bfloat16 hl = __float2bfloat16(hn - __bfloat162float(hh));
                hout_h[hidx] = hh;
                hout_l[hidx] = hl;
                if (dh) {
                    dh[(size_t)t * (B_SZ * H_SZ) + hidx] = hh;
                    dl[(size_t)t * (B_SZ * H_SZ) + hidx] = hl;
                }
            }
        }
        grid_bar_();
        {   // swap parity
            const __nv_bfloat16* th = hin_h; const __nv_bfloat16* tl = hin_l;
            hin_h = hout_h; hin_l = hout_l;
            hout_h = (__nv_bfloat16*)th; hout_l = (__nv_bfloat16*)tl;
        }
    }
}

// ============================ host launcher ============================
extern "C" void kernel_launch(void* const* d_in, const int* in_sizes, int n_in,
                              void* d_out, int out_size)
{
    (void)in_sizes; (void)n_in; (void)out_size;
    const float* frames = (const float*)d_in[0];
    const int*   ids    = (const int*)d_in[1];
    const float* emb    = (const float*)d_in[2];
    const float* W_enc  = (const float*)d_in[3];
    const float* b_enc  = (const float*)d_in[4];
    const float* W_dec  = (const float*)d_in[5];
    const float* b_dec  = (const float*)d_in[6];
    const float* W_out  = (const float*)d_in[7];
    const float* b_out  = (const float*)d_in[8];
    float* out = (float*)d_out;

    float *Xge, *Xgd;
    __nv_bfloat16 *Afh, *Afl, *Beh, *Bel, *Adh, *Adl, *Bdh, *Bdl, *Dhh, *Dhl, *Boh, *Bol;
    __nv_bfloat16 *WhT, *hl;
    cudaGetSymbolAddress((void**)&Xge, g_Xg_enc);
    cudaGetSymbolAddress((void**)&Xgd, g_Xg_dec);
    cudaGetSymbolAddress((void**)&WhT, g_WhT);
    cudaGetSymbolAddress((void**)&hl,  g_hl);
    cudaGetSymbolAddress((void**)&Afh, g_Afr_h);  cudaGetSymbolAddress((void**)&Afl, g_Afr_l);
    cudaGetSymbolAddress((void**)&Beh, g_Bte_h);  cudaGetSymbolAddress((void**)&Bel, g_Bte_l);
    cudaGetSymbolAddress((void**)&Adh, g_Ad_h);   cudaGetSymbolAddress((void**)&Adl, g_Ad_l);
    cudaGetSymbolAddress((void**)&Bdh, g_Btd_h);  cudaGetSymbolAddress((void**)&Bdl, g_Btd_l);
    cudaGetSymbolAddress((void**)&Dhh, g_Dh_h);   cudaGetSymbolAddress((void**)&Dhl, g_Dh_l);
    cudaGetSymbolAddress((void**)&Boh, g_Bto_h);  cudaGetSymbolAddress((void**)&Bol, g_Bto_l);

    const size_t WL = (size_t)G4 * H_SZ;          // one WhT limb
    __nv_bfloat16* WTeh = WhT;            __nv_bfloat16* WTel = WhT + WL;
    __nv_bfloat16* WTdh = WhT + 2 * WL;   __nv_bfloat16* WTdl = WhT + 3 * WL;
    const size_t HL = (size_t)B_SZ * H_SZ;        // one h limb
    __nv_bfloat16* h0h = hl;             __nv_bfloat16* h0l = hl + HL;
    __nv_bfloat16* h1h = hl + 2 * HL;    __nv_bfloat16* h1l = hl + 3 * HL;

    cudaFuncSetAttribute(gemm_ts<0>, cudaFuncAttributeMaxDynamicSharedMemorySize, GTS_SMEM);
    cudaFuncSetAttribute(gemm_ts<1>, cudaFuncAttributeMaxDynamicSharedMemorySize, GTS_SMEM);
    cudaFuncSetAttribute(lstm_rec,   cudaFuncAttributeMaxDynamicSharedMemorySize, REC_SMEM);

    // conversions
    conv_frames<<<M_ENC, 256>>>(frames, Afh, Afl);
    conv_w_t<<<dim3(D_IN / 32, G4 / 32), dim3(32, 8)>>>(W_enc, G4, D_IN, D_IN, G4, Beh, Bel);
    conv_w_t<<<dim3(D_WP / 32, G4 / 32), dim3(32, 8)>>>(W_dec, G4, D_W, D_WP, G4, Bdh, Bdl);
    conv_w_t<<<dim3(H_SZ / 32, 512 / 32), dim3(32, 8)>>>(W_out, D_W, H_SZ, H_SZ, D_W, Boh, Bol);
    conv_whT<<<dim3(16, 16, 4), dim3(32, 8)>>>(W_enc + (size_t)D_IN * G4, WTeh, WTel);
    conv_whT<<<dim3(16, 16, 4), dim3(32, 8)>>>(W_dec + (size_t)D_W * G4, WTdh, WTdl);
    gather_conv<<<M_DEC, 128>>>(ids, emb, Adh, Adl);

    // 1. Encoder input gates
    gemm_ts<0><<<dim3(G4 / 128, M_ENC / 128), 256, GTS_SMEM>>>(
        Afh, Afl, Beh, Bel, b_enc, Xge, G4, D_IN);

    // 2. Encoder recurrence (64 steps; step0 writes parity0 -> final h in parity1)
    lstm_rec<<<dim3(32, 1, 4), 256, REC_SMEM>>>(
        WTeh, WTel, Xge, T_ENC, 1, h1h, h1l, h0h, h0l, nullptr, nullptr);

    // 3. Decoder input gates
    gemm_ts<0><<<dim3(G4 / 128, M_DEC / 128), 256, GTS_SMEM>>>(
        Adh, Adl, Bdh, Bdl, b_dec, Xgd, G4, D_WP);

    // 4. Decoder recurrence (32 steps from encoder state in parity1), writes h limbs per t
    lstm_rec<<<dim3(32, 1, 4), 256, REC_SMEM>>>(
        WTdh, WTdl, Xgd, T_DEC, 0, h1h, h1l, h0h, h0l, Dhh, Dhl);

    // 5. Output projection, permuted store into [B, T_dec, D_w]
    gemm_ts<1><<<dim3(3, M_DEC / 128), 256, GTS_SMEM>>>(
        Dhh, Dhl, Boh, Bol, b_out, out, D_W, H_SZ);
}